// round 1
// baseline (speedup 1.0000x reference)
#include <cuda_runtime.h>
#include <math.h>

// Problem constants
#define BB   32
#define CC   512
#define WH   1024              // 32*32
#define NN   32768             // B*W*H rows
#define KK   1024              // codes
#define QE   16777216          // 32*512*32*32 quantized elements

// Scratch (device globals: allocation-free per harness rules)
__device__ float g_xs[(size_t)NN * CC];   // xs in [c][n] layout: g_xs[c*NN + n]
__device__ float g_x2[NN];                // per-row (sum xs^2) + 512
__device__ int   g_idx[NN];
__device__ int   g_cnt[KK];

// ---------------------------------------------------------------------------
// K1: xs = 2*sigmoid(100x)-1, transposed into [c][n] layout (n = b*1024 + w*32+h)
// ---------------------------------------------------------------------------
__global__ void prep_xs_kernel(const float* __restrict__ x) {
    int i = blockIdx.x * blockDim.x + threadIdx.x;   // 0 .. QE-1
    float v = x[i];
    float s = 1.0f / (1.0f + __expf(-100.0f * v));
    float xs = fmaf(2.0f, s, -1.0f);
    int p  = i & 1023;          // w*32+h
    int bc = i >> 10;
    int c  = bc & 511;
    int b  = bc >> 9;
    g_xs[(size_t)c * NN + b * 1024 + p] = xs;
}

// ---------------------------------------------------------------------------
// K2: per-row ||xs||^2 + 512  (block = 64 rows)
// ---------------------------------------------------------------------------
__global__ void x2_kernel() {
    __shared__ float sred[256];
    int tid = threadIdx.x;
    int rowbase = blockIdx.x * 64;
    int r  = tid & 63;
    int c0 = tid >> 6;          // 0..3
    float acc = 0.0f;
    for (int c = c0; c < CC; c += 4) {
        float v = g_xs[(size_t)c * NN + rowbase + r];
        acc = fmaf(v, v, acc);
    }
    sred[tid] = acc;
    __syncthreads();
    if (tid < 64) {
        float t = ((sred[tid] + sred[tid + 64]) + sred[tid + 128]) + sred[tid + 192];
        g_x2[rowbase + tid] = t + 512.0f;   // fold in ||cb||^2 = 512 (exact for bipolar)
    }
}

// ---------------------------------------------------------------------------
// K3: fused GEMM + argmin.  Tile 64 rows x 64 codes, 256 threads, 4x4/thread.
// d_k = fma(-2, dot_k, x2+512); argmin with first-index tie-break.
// ---------------------------------------------------------------------------
__global__ void __launch_bounds__(256) gemm_argmin_kernel(const float* __restrict__ cb) {
    __shared__ float As[32 * 68];
    __shared__ float Bs[32 * 68];

    int tid = threadIdx.x;
    int tx = tid & 15;          // code group
    int ty = tid >> 4;          // row group
    int rowbase = blockIdx.x * 64;

    // A-loader constants
    int la_r = tid & 63;
    int la_c = tid >> 6;        // 0..3, +4 per step
    // B-loader constants
    int lb_c = tid & 31;
    int lb_k = tid >> 5;        // 0..7, +8 per step

    float A4[4];
#pragma unroll
    for (int i = 0; i < 4; i++) A4[i] = g_x2[rowbase + ty * 4 + i];

    float bestD[4] = {INFINITY, INFINITY, INFINITY, INFINITY};
    int   bestI[4] = {0, 0, 0, 0};

    for (int kt = 0; kt < KK; kt += 64) {
        float acc[4][4];
#pragma unroll
        for (int i = 0; i < 4; i++)
#pragma unroll
            for (int j = 0; j < 4; j++) acc[i][j] = 0.0f;

        for (int cc = 0; cc < CC; cc += 32) {
            // load A tile [32c x 64r]
#pragma unroll
            for (int l = 0; l < 8; l++) {
                int c = la_c + l * 4;
                As[c * 68 + la_r] = g_xs[(size_t)(cc + c) * NN + rowbase + la_r];
            }
            // load B tile [32c x 64k] (transposed store)
#pragma unroll
            for (int l = 0; l < 8; l++) {
                int k = lb_k + l * 8;
                Bs[lb_c * 68 + k] = cb[(kt + k) * CC + cc + lb_c];
            }
            __syncthreads();

#pragma unroll
            for (int c = 0; c < 32; c++) {
                float4 av = *(const float4*)&As[c * 68 + ty * 4];
                float4 bv = *(const float4*)&Bs[c * 68 + tx * 4];
                acc[0][0] = fmaf(av.x, bv.x, acc[0][0]);
                acc[0][1] = fmaf(av.x, bv.y, acc[0][1]);
                acc[0][2] = fmaf(av.x, bv.z, acc[0][2]);
                acc[0][3] = fmaf(av.x, bv.w, acc[0][3]);
                acc[1][0] = fmaf(av.y, bv.x, acc[1][0]);
                acc[1][1] = fmaf(av.y, bv.y, acc[1][1]);
                acc[1][2] = fmaf(av.y, bv.z, acc[1][2]);
                acc[1][3] = fmaf(av.y, bv.w, acc[1][3]);
                acc[2][0] = fmaf(av.z, bv.x, acc[2][0]);
                acc[2][1] = fmaf(av.z, bv.y, acc[2][1]);
                acc[2][2] = fmaf(av.z, bv.z, acc[2][2]);
                acc[2][3] = fmaf(av.z, bv.w, acc[2][3]);
                acc[3][0] = fmaf(av.w, bv.x, acc[3][0]);
                acc[3][1] = fmaf(av.w, bv.y, acc[3][1]);
                acc[3][2] = fmaf(av.w, bv.z, acc[3][2]);
                acc[3][3] = fmaf(av.w, bv.w, acc[3][3]);
            }
            __syncthreads();
        }

        // epilogue: local argmin over 4 codes, then shfl-reduce across 16 tx lanes
#pragma unroll
        for (int i = 0; i < 4; i++) {
            float bd = INFINITY;
            int   bi = 0;
#pragma unroll
            for (int j = 0; j < 4; j++) {
                float d = fmaf(-2.0f, acc[i][j], A4[i]);
                if (d < bd) { bd = d; bi = kt + tx * 4 + j; }
            }
#pragma unroll
            for (int off = 8; off > 0; off >>= 1) {
                float od = __shfl_xor_sync(0xffffffffu, bd, off);
                int   oi = __shfl_xor_sync(0xffffffffu, bi, off);
                if (od < bd || (od == bd && oi < bi)) { bd = od; bi = oi; }
            }
            if (tx == 0 && bd < bestD[i]) { bestD[i] = bd; bestI[i] = bi; }
        }
    }

    if (tx == 0) {
#pragma unroll
        for (int i = 0; i < 4; i++) g_idx[rowbase + ty * 4 + i] = bestI[i];
    }
}

// ---------------------------------------------------------------------------
// K4: gather codebook rows and scatter to [B,C,W,H] output
// ---------------------------------------------------------------------------
__global__ void gather_kernel(const float* __restrict__ cb, float* __restrict__ out) {
    int t = blockIdx.x * blockDim.x + threadIdx.x;   // 0 .. NN*128-1
    int n  = t & (NN - 1);
    int cg = t >> 15;           // 0..127 (group of 4 channels)
    int idx = g_idx[n];
    float4 v = ((const float4*)cb)[idx * 128 + cg];
    int b = n >> 10, p = n & 1023;
    int c = cg << 2;
    float* o = out + (((size_t)(b * 512 + c)) << 10) + p;
    o[0]    = v.x;
    o[1024] = v.y;
    o[2048] = v.z;
    o[3072] = v.w;
}

// ---------------------------------------------------------------------------
// K5: histogram (counts zeroed by K0)
// ---------------------------------------------------------------------------
__global__ void zero_counts_kernel() {
    int k = blockIdx.x * blockDim.x + threadIdx.x;
    if (k < KK) g_cnt[k] = 0;
}

__global__ void hist_kernel() {
    __shared__ int h[KK];
    int tid = threadIdx.x;
    for (int i = tid; i < KK; i += 256) h[i] = 0;
    __syncthreads();
    int base = blockIdx.x * 1024;
    for (int i = tid; i < 1024; i += 256) atomicAdd(&h[g_idx[base + i]], 1);
    __syncthreads();
    for (int i = tid; i < KK; i += 256) if (h[i]) atomicAdd(&g_cnt[i], h[i]);
}

// ---------------------------------------------------------------------------
// K6: entropy -> perplexity_loss, loss
// ---------------------------------------------------------------------------
__global__ void entropy_kernel(float* __restrict__ out_scalars) {
    __shared__ float s[256];
    int tid = threadIdx.x;
    float acc = 0.0f;
    for (int k = tid; k < KK; k += 256) {
        int c = g_cnt[k];
        if (c > 0) {
            float p = (float)c / 32768.0f;
            acc += p * logf(p);
        }
    }
    s[tid] = acc;
    __syncthreads();
    for (int o = 128; o > 0; o >>= 1) {
        if (tid < o) s[tid] += s[tid + o];
        __syncthreads();
    }
    if (tid == 0) {
        float entropy = -s[0];
        float perp = expf(entropy);
        float pl = 1.0f / perp;
        out_scalars[0] = pl;            // perplexity_loss
        out_scalars[1] = 0.25f * pl;    // loss = BETA * perplexity_loss
    }
}

// ---------------------------------------------------------------------------
extern "C" void kernel_launch(void* const* d_in, const int* in_sizes, int n_in,
                              void* d_out, int out_size) {
    const float* x  = (const float*)d_in[0];
    const float* cb = (const float*)d_in[1];
    float* out = (float*)d_out;

    zero_counts_kernel<<<4, 256>>>();
    prep_xs_kernel<<<QE / 256, 256>>>(x);
    x2_kernel<<<NN / 64, 256>>>();
    gemm_argmin_kernel<<<NN / 64, 256>>>(cb);
    gather_kernel<<<(NN * 128) / 256, 256>>>(cb, out);
    hist_kernel<<<NN / 1024, 256>>>();
    if (out_size >= QE + 2) {
        entropy_kernel<<<1, 256>>>(out + QE);
    }
}

// round 3
// speedup vs baseline: 2.2651x; 2.2651x over previous
#include <cuda_runtime.h>
#include <cuda_bf16.h>
#include <cstdint>
#include <math.h>

// Problem constants
#define NN   32768
#define KK   1024
#define QE   16777216

// GEMM tiling
#define M_TILE 128
#define N_TILE 128
#define N_TILES 8
#define K_SLABS 16             // 512 ch / 32 per slab
#define ROW_STRIDE 80          // bytes per smem row (64B data + 16B pad; 5 mod 8 -> conflict-free ldsm)
#define A_PHASE_BYTES (128 * ROW_STRIDE)        // 10240
#define STAGE_BYTES (4 * A_PHASE_BYTES)         // 3 A phases + 1 B = 40960
#define GEMM_SMEM (2 * STAGE_BYTES)             // 81920
#define PREP_SMEM (65664 + 32896 + 1024)

// Scratch (device globals; allocation-free). Slab-major layouts:
// g_hi[slab 16][row 32768][16 u32]  (16 u32 = 32 ch bf16 = 64B)
__device__ uint32_t g_hi[16 * NN * 16];
__device__ uint32_t g_mid[16 * NN * 16];
__device__ uint32_t g_lo[16 * NN * 16];
__device__ uint32_t g_cbb[16 * KK * 16];   // [slab][code][16 u32]
__device__ float g_x2[NN];
__device__ unsigned long long g_best[NN];
__device__ int g_cnt[KK];

__device__ __forceinline__ uint32_t smem_u32(const void* p) {
    return (uint32_t)__cvta_generic_to_shared(p);
}

#define LDSM4(r0, r1, r2, r3, addr)                                           \
    asm volatile("ldmatrix.sync.aligned.m8n8.x4.shared.b16 {%0,%1,%2,%3}, [%4];" \
                 : "=r"(r0), "=r"(r1), "=r"(r2), "=r"(r3) : "r"(addr))

#define MMA16816(C, A, B0, B1)                                                \
    asm volatile("mma.sync.aligned.m16n8k16.row.col.f32.bf16.bf16.f32 "       \
                 "{%0,%1,%2,%3},{%4,%5,%6,%7},{%8,%9},{%0,%1,%2,%3};"         \
                 : "+f"((C)[0]), "+f"((C)[1]), "+f"((C)[2]), "+f"((C)[3])     \
                 : "r"((A)[0]), "r"((A)[1]), "r"((A)[2]), "r"((A)[3]),        \
                   "r"(B0), "r"(B1))

#define CP_ASYNC16(dst, src)                                                  \
    asm volatile("cp.async.cg.shared.global [%0], [%1], 16;" :: "r"(dst), "l"(src))
#define CP_COMMIT() asm volatile("cp.async.commit_group;")
#define CP_WAIT1()  asm volatile("cp.async.wait_group 1;")
#define CP_WAIT0()  asm volatile("cp.async.wait_group 0;")

// ---------------------------------------------------------------------------
// K0a: init best keys
// ---------------------------------------------------------------------------
__global__ void init_best_kernel() {
    int i = blockIdx.x * 256 + threadIdx.x;
    g_best[i] = 0xFFFFFFFFFFFFFFFFull;
}
__global__ void zero_counts_kernel() {
    int k = blockIdx.x * blockDim.x + threadIdx.x;
    if (k < KK) g_cnt[k] = 0;
}

// ---------------------------------------------------------------------------
// K0b: codebook fp32 -> bf16, slab-major
// ---------------------------------------------------------------------------
__global__ void cb_bf16_kernel(const float* __restrict__ cb) {
    int i = blockIdx.x * 256 + threadIdx.x;   // 0..262143 (code*256 + cw)
    int code = i >> 8, cw = i & 255;
    float2 v = ((const float2*)cb)[i];
    __nv_bfloat162 b2 = __floats2bfloat162_rn(v.x, v.y);
    uint32_t u; memcpy(&u, &b2, 4);
    g_cbb[(((size_t)(cw >> 4)) * KK + code) * 16 + (cw & 15)] = u;
}

// ---------------------------------------------------------------------------
// K1: prep — xs = 2*sigmoid(100x)-1, 3-way bf16 split (hi+mid+lo == xs to
// ~2^-25 rel), transpose to row-major slab-major, plus ||xs||^2 + 512.
// ---------------------------------------------------------------------------
__global__ void __launch_bounds__(256) prep_kernel(const float* __restrict__ x) {
    extern __shared__ char sm[];
    uint32_t* s_hm = (uint32_t*)sm;                       // [32][513]
    unsigned short* s_lo = (unsigned short*)(sm + 65664); // [32][514]
    float* s_red = (float*)(sm + 65664 + 32896);          // [256]

    int tid = threadIdx.x;
    int b   = blockIdx.x >> 5;
    int p0  = (blockIdx.x & 31) * 32;
    int p   = tid & 31;
    int cg  = tid >> 5;

    float acc = 0.0f;
#pragma unroll 4
    for (int cc = 0; cc < 64; cc++) {
        int c = cc * 8 + cg;
        float v = x[(b * 512 + c) * 1024 + p0 + p];
        float s = 1.0f / (1.0f + __expf(-100.0f * v));
        float xs = fmaf(2.0f, s, -1.0f);
        acc = fmaf(xs, xs, acc);
        __nv_bfloat16 h = __float2bfloat16_rn(xs);
        float r1 = xs - __bfloat162float(h);
        __nv_bfloat16 m = __float2bfloat16_rn(r1);
        float r2 = r1 - __bfloat162float(m);
        __nv_bfloat16 l = __float2bfloat16_rn(r2);
        s_hm[p * 513 + c] = (uint32_t)__bfloat16_as_ushort(h)
                          | ((uint32_t)__bfloat16_as_ushort(m) << 16);
        s_lo[p * 514 + c] = __bfloat16_as_ushort(l);
    }
    s_red[tid] = acc;
    __syncthreads();

    if (tid < 32) {
        float t = 0.0f;
#pragma unroll
        for (int g = 0; g < 8; g++) t += s_red[g * 32 + tid];
        g_x2[b * 1024 + p0 + tid] = t + 512.0f;
    }

    int nb = b * 1024 + p0;
#pragma unroll 4
    for (int t = tid; t < 32 * 256; t += 256) {
        int r  = t >> 8;
        int cw = t & 255;
        uint32_t hm0 = s_hm[r * 513 + 2 * cw];
        uint32_t hm1 = s_hm[r * 513 + 2 * cw + 1];
        uint32_t hi_pair  = (hm0 & 0xffffu) | (hm1 << 16);
        uint32_t mid_pair = (hm0 >> 16) | (hm1 & 0xffff0000u);
        uint32_t lo_pair  = (uint32_t)s_lo[r * 514 + 2 * cw]
                          | ((uint32_t)s_lo[r * 514 + 2 * cw + 1] << 16);
        size_t gi = (((size_t)(cw >> 4)) * NN + nb + r) * 16 + (cw & 15);
        g_hi[gi]  = hi_pair;
        g_mid[gi] = mid_pair;
        g_lo[gi]  = lo_pair;
    }
}

// ---------------------------------------------------------------------------
// K2: HMMA GEMM + fused argmin. CTA = 128 rows x 1024 codes (8 N-tiles).
// 8 warps (4M x 2N), warp tile 32x64. K: 16 slabs of 32ch x 3 split phases.
// ---------------------------------------------------------------------------
__global__ void __launch_bounds__(256, 2) gemm_hmma_kernel() {
    extern __shared__ char sm[];
    uint32_t smb = smem_u32(sm);

    int tid = threadIdx.x;
    int lane = tid & 31;
    int wid = tid >> 5;
    int wy = wid & 3;
    int wx = wid >> 2;
    int rowbase = blockIdx.x * M_TILE;

    // ldmatrix per-thread address bases
    uint32_t tbaseA = (uint32_t)((wy * 32 + ((lane >> 3) & 1) * 8 + (lane & 7)) * ROW_STRIDE
                                 + (lane >> 4) * 16);
    uint32_t tbaseB = (uint32_t)(((lane >> 4) * 8 + (lane & 7)) * ROW_STRIDE
                                 + ((lane >> 3) & 1) * 16);

    const char* gA[3] = { (const char*)g_hi, (const char*)g_mid, (const char*)g_lo };

    float x2v[4];
#pragma unroll
    for (int s = 0; s < 4; s++) x2v[s] = g_x2[rowbase + wy * 32 + (lane >> 2) + s * 8];

    float bD[4] = {INFINITY, INFINITY, INFINITY, INFINITY};
    int   bI[4] = {0, 0, 0, 0};

    for (int nt = 0; nt < N_TILES; nt++) {
        float acc[2][8][4];
#pragma unroll
        for (int m = 0; m < 2; m++)
#pragma unroll
            for (int nf = 0; nf < 8; nf++)
#pragma unroll
                for (int j = 0; j < 4; j++) acc[m][nf][j] = 0.0f;

        // --- async loader lambda-equivalent (macro-ish) ---
        // chunk id = tid + i*256; part = id>>9 (0..2 A phases, 3 B);
        // r = (id&511)>>2; c = id&3
#define ISSUE_SLAB(slab, stage)                                               \
        {                                                                     \
            uint32_t dstbase = smb + (stage) * STAGE_BYTES;                   \
            _Pragma("unroll")                                                 \
            for (int i = 0; i < 8; i++) {                                     \
                int id = tid + i * 256;                                       \
                int part = id >> 9;                                           \
                int r = (id & 511) >> 2;                                      \
                int c = id & 3;                                               \
                uint32_t dst = dstbase + part * A_PHASE_BYTES                 \
                             + r * ROW_STRIDE + c * 16;                       \
                const char* src;                                              \
                if (part < 3)                                                 \
                    src = gA[part] + ((size_t)(slab) * NN + rowbase + r) * 64 \
                        + c * 16;                                             \
                else                                                          \
                    src = (const char*)g_cbb                                  \
                        + ((size_t)(slab) * KK + nt * N_TILE + r) * 64        \
                        + c * 16;                                             \
                CP_ASYNC16(dst, src);                                         \
            }                                                                 \
            CP_COMMIT();                                                      \
        }

        ISSUE_SLAB(0, 0);

        for (int s = 0; s < K_SLABS; s++) {
            if (s + 1 < K_SLABS) ISSUE_SLAB(s + 1, (s + 1) & 1);
            if (s + 1 < K_SLABS) { CP_WAIT1(); } else { CP_WAIT0(); }
            __syncthreads();

            uint32_t sA = smb + (s & 1) * STAGE_BYTES;
            uint32_t sB = sA + 3 * A_PHASE_BYTES;
#pragma unroll
            for (int kk = 0; kk < 2; kk++) {
                uint32_t b[8][2];
#pragma unroll
                for (int q = 0; q < 4; q++) {
                    uint32_t addr = sB + (uint32_t)((wx * 64 + q * 16) * ROW_STRIDE)
                                  + tbaseB + kk * 32;
                    LDSM4(b[2 * q][0], b[2 * q][1], b[2 * q + 1][0], b[2 * q + 1][1], addr);
                }
#pragma unroll
                for (int p = 0; p < 3; p++) {
                    uint32_t a0[4], a1[4];
                    uint32_t aaddr = sA + p * A_PHASE_BYTES + tbaseA + kk * 32;
                    LDSM4(a0[0], a0[1], a0[2], a0[3], aaddr);
                    LDSM4(a1[0], a1[1], a1[2], a1[3], aaddr + 16 * ROW_STRIDE);
#pragma unroll
                    for (int nf = 0; nf < 8; nf++) {
                        MMA16816(acc[0][nf], a0, b[nf][0], b[nf][1]);
                        MMA16816(acc[1][nf], a1, b[nf][0], b[nf][1]);
                    }
                }
            }
            __syncthreads();
        }
#undef ISSUE_SLAB

        // epilogue: fused argmin over this N-tile (ascending index order)
        int colbase = nt * N_TILE + wx * 64 + (lane & 3) * 2;
#pragma unroll
        for (int nf = 0; nf < 8; nf++) {
            int cidx = colbase + nf * 8;
#pragma unroll
            for (int m = 0; m < 2; m++) {
                float d0 = fmaf(-2.0f, acc[m][nf][0], x2v[m * 2]);
                float d1 = fmaf(-2.0f, acc[m][nf][1], x2v[m * 2]);
                float d2 = fmaf(-2.0f, acc[m][nf][2], x2v[m * 2 + 1]);
                float d3 = fmaf(-2.0f, acc[m][nf][3], x2v[m * 2 + 1]);
                if (d0 < bD[m * 2])     { bD[m * 2] = d0;     bI[m * 2] = cidx; }
                if (d1 < bD[m * 2])     { bD[m * 2] = d1;     bI[m * 2] = cidx + 1; }
                if (d2 < bD[m * 2 + 1]) { bD[m * 2 + 1] = d2; bI[m * 2 + 1] = cidx; }
                if (d3 < bD[m * 2 + 1]) { bD[m * 2 + 1] = d3; bI[m * 2 + 1] = cidx + 1; }
            }
        }
    }

    // reduce across the 4 lanes sharing each row
#pragma unroll
    for (int off = 1; off <= 2; off <<= 1) {
#pragma unroll
        for (int s = 0; s < 4; s++) {
            float od = __shfl_xor_sync(0xffffffffu, bD[s], off);
            int   oi = __shfl_xor_sync(0xffffffffu, bI[s], off);
            if (od < bD[s] || (od == bD[s] && oi < bI[s])) { bD[s] = od; bI[s] = oi; }
        }
    }

    if ((lane & 3) == 0) {
#pragma unroll
        for (int s = 0; s < 4; s++) {
            int row = rowbase + wy * 32 + (lane >> 2) + s * 8;
            uint32_t u = __float_as_uint(bD[s]);
            u = (u & 0x80000000u) ? ~u : (u | 0x80000000u);
            unsigned long long key = ((unsigned long long)u << 32) | (unsigned)bI[s];
            atomicMin(&g_best[row], key);
        }
    }
}

// ---------------------------------------------------------------------------
// K3: gather codebook rows -> [B,C,W,H]
// ---------------------------------------------------------------------------
__global__ void gather_kernel(const float* __restrict__ cb, float* __restrict__ out) {
    int t = blockIdx.x * blockDim.x + threadIdx.x;
    int n  = t & (NN - 1);
    int cg = t >> 15;
    int idx = (int)(unsigned)(g_best[n] & 0xffffffffu);
    float4 v = ((const float4*)cb)[idx * 128 + cg];
    int b = n >> 10, p = n & 1023;
    int c = cg << 2;
    float* o = out + (((size_t)(b * 512 + c)) << 10) + p;
    o[0]    = v.x;
    o[1024] = v.y;
    o[2048] = v.z;
    o[3072] = v.w;
}

// ---------------------------------------------------------------------------
// K4/K5: histogram + entropy
// ---------------------------------------------------------------------------
__global__ void hist_kernel() {
    __shared__ int h[KK];
    int tid = threadIdx.x;
    for (int i = tid; i < KK; i += 256) h[i] = 0;
    __syncthreads();
    int base = blockIdx.x * 1024;
    for (int i = tid; i < 1024; i += 256)
        atomicAdd(&h[(int)(unsigned)(g_best[base + i] & 0xffffffffu)], 1);
    __syncthreads();
    for (int i = tid; i < KK; i += 256) if (h[i]) atomicAdd(&g_cnt[i], h[i]);
}

__global__ void entropy_kernel(float* __restrict__ out_scalars) {
    __shared__ float s[256];
    int tid = threadIdx.x;
    float acc = 0.0f;
    for (int k = tid; k < KK; k += 256) {
        int c = g_cnt[k];
        if (c > 0) {
            float p = (float)c / 32768.0f;
            acc += p * logf(p);
        }
    }
    s[tid] = acc;
    __syncthreads();
    for (int o = 128; o > 0; o >>= 1) {
        if (tid < o) s[tid] += s[tid + o];
        __syncthreads();
    }
    if (tid == 0) {
        float entropy = -s[0];
        float perp = expf(entropy);
        float pl = 1.0f / perp;
        out_scalars[0] = pl;
        out_scalars[1] = 0.25f * pl;
    }
}

// ---------------------------------------------------------------------------
extern "C" void kernel_launch(void* const* d_in, const int* in_sizes, int n_in,
                              void* d_out, int out_size) {
    const float* x  = (const float*)d_in[0];
    const float* cb = (const float*)d_in[1];
    float* out = (float*)d_out;

    cudaFuncSetAttribute(prep_kernel, cudaFuncAttributeMaxDynamicSharedMemorySize, PREP_SMEM);
    cudaFuncSetAttribute(gemm_hmma_kernel, cudaFuncAttributeMaxDynamicSharedMemorySize, GEMM_SMEM);

    init_best_kernel<<<NN / 256, 256>>>();
    zero_counts_kernel<<<4, 256>>>();
    cb_bf16_kernel<<<1024, 256>>>(cb);
    prep_kernel<<<1024, 256, PREP_SMEM>>>(x);
    gemm_hmma_kernel<<<NN / M_TILE, 256, GEMM_SMEM>>>();
    gather_kernel<<<(NN * 128) / 256, 256>>>(cb, out);
    hist_kernel<<<NN / 1024, 256>>>();
    if (out_size >= QE + 2) {
        entropy_kernel<<<1, 256>>>(out + QE);
    }
}

// round 5
// speedup vs baseline: 3.3755x; 1.4902x over previous
#include <cuda_runtime.h>
#include <cuda_bf16.h>
#include <cstdint>
#include <math.h>

// Problem constants
#define NN   32768
#define KK   1024
#define QE   16777216

// GEMM tiling: CTA = 128 rows x 256 codes, full K (512ch x 3 split phases)
#define M_TILE 128
#define N_TILE 256
#define K_SLABS 16             // 512 ch / 32 per slab
#define ROW_STRIDE 80          // 64B data + 16B pad (conflict-free ldsm)
#define A_PHASE_BYTES (128 * ROW_STRIDE)            // 10240
#define B_PHASE_BYTES (256 * ROW_STRIDE)            // 20480
#define STAGE_BYTES (3 * A_PHASE_BYTES + B_PHASE_BYTES)  // 51200
#define GEMM_SMEM (2 * STAGE_BYTES)                 // 102400
#define PREP_SMEM (65664 + 32896 + 2048)

// Scratch (device globals; allocation-free). Slab-major:
// g_hi[slab 16][row 32768][16 u32] (16 u32 = 32 ch bf16 = 64B)
__device__ uint32_t g_hi[16 * NN * 16];
__device__ uint32_t g_mid[16 * NN * 16];
__device__ uint32_t g_lo[16 * NN * 16];
__device__ uint32_t g_cbb[16 * KK * 16];   // [slab][code][16 u32]
__device__ float g_x2[NN];
__device__ unsigned long long g_best[NN];
__device__ int g_cnt[KK];

__device__ __forceinline__ uint32_t smem_u32(const void* p) {
    return (uint32_t)__cvta_generic_to_shared(p);
}

#define LDSM4(r0, r1, r2, r3, addr)                                           \
    asm volatile("ldmatrix.sync.aligned.m8n8.x4.shared.b16 {%0,%1,%2,%3}, [%4];" \
                 : "=r"(r0), "=r"(r1), "=r"(r2), "=r"(r3) : "r"(addr))

#define MMA16816(C, A, B0, B1)                                                \
    asm volatile("mma.sync.aligned.m16n8k16.row.col.f32.bf16.bf16.f32 "       \
                 "{%0,%1,%2,%3},{%4,%5,%6,%7},{%8,%9},{%0,%1,%2,%3};"         \
                 : "+f"((C)[0]), "+f"((C)[1]), "+f"((C)[2]), "+f"((C)[3])     \
                 : "r"((A)[0]), "r"((A)[1]), "r"((A)[2]), "r"((A)[3]),        \
                   "r"(B0), "r"(B1))

#define CP_ASYNC16(dst, src)                                                  \
    asm volatile("cp.async.cg.shared.global [%0], [%1], 16;" :: "r"(dst), "l"(src))
#define CP_COMMIT() asm volatile("cp.async.commit_group;")
#define CP_WAIT1()  asm volatile("cp.async.wait_group 1;")
#define CP_WAIT0()  asm volatile("cp.async.wait_group 0;")

// ---------------------------------------------------------------------------
__global__ void init_best_kernel() {
    int i = blockIdx.x * 256 + threadIdx.x;
    g_best[i] = 0xFFFFFFFFFFFFFFFFull;
}
__global__ void zero_counts_kernel() {
    int k = blockIdx.x * blockDim.x + threadIdx.x;
    if (k < KK) g_cnt[k] = 0;
}

// ---------------------------------------------------------------------------
// codebook fp32 -> bf16, slab-major
// ---------------------------------------------------------------------------
__global__ void cb_bf16_kernel(const float* __restrict__ cb) {
    int i = blockIdx.x * 256 + threadIdx.x;   // code*256 + cw
    int code = i >> 8, cw = i & 255;
    float2 v = ((const float2*)cb)[i];
    __nv_bfloat162 b2 = __floats2bfloat162_rn(v.x, v.y);
    uint32_t u; memcpy(&u, &b2, 4);
    g_cbb[(((size_t)(cw >> 4)) * KK + code) * 16 + (cw & 15)] = u;
}

// ---------------------------------------------------------------------------
// prep: xs = tanh(50x) (== 2*sigmoid(100x)-1) via FMA-only exp2 + Newton rcp,
// 3-way bf16 split, transpose to slab-major, ||xs||^2 + 512.
// 512 threads: 32 p-values x 16 channel-groups.
// ---------------------------------------------------------------------------
__global__ void __launch_bounds__(512, 2) prep_kernel(const float* __restrict__ x) {
    extern __shared__ char sm[];
    uint32_t* s_hm = (uint32_t*)sm;                       // [32][513]
    unsigned short* s_lo = (unsigned short*)(sm + 65664); // [32][514]
    float* s_red = (float*)(sm + 65664 + 32896);          // [512]

    int tid = threadIdx.x;
    int b   = blockIdx.x >> 5;
    int p0  = (blockIdx.x & 31) * 32;
    int p   = tid & 31;
    int cg  = tid >> 5;         // 0..15

    float acc = 0.0f;
#pragma unroll 4
    for (int j = 0; j < 32; j++) {
        int c = j * 16 + cg;
        float v = x[(b * 512 + c) * 1024 + p0 + p];
        // m = exp(-100|v|) = 2^t, t = -144.2695*|v|  (clamped at -30)
        float t = fmaxf(-144.26950408889634f * fabsf(v), -30.0f);
        float kf = t + 12582912.0f;                 // round-to-nearest int
        int   ni = __float_as_int(kf) - 0x4B400000; // n in [-30, 0]
        float f  = t - (kf - 12582912.0f);          // f in [-0.5, 0.5]
        // 2^f, degree-7 Taylor in f (rel err ~5e-9)
        float pe = 1.52527338e-5f;
        pe = fmaf(pe, f, 1.54035304e-4f);
        pe = fmaf(pe, f, 1.33335581e-3f);
        pe = fmaf(pe, f, 9.61812911e-3f);
        pe = fmaf(pe, f, 5.55041087e-2f);
        pe = fmaf(pe, f, 2.40226507e-1f);
        pe = fmaf(pe, f, 6.93147181e-1f);
        pe = fmaf(pe, f, 1.0f);
        float m = __int_as_float(__float_as_int(pe) + (ni << 23));
        // r = 1/(1+m) by Newton. den in [1,2]; minimax linear seed on [1,2]:
        // r0 = 1.45710678 - 0.5*den, |1 - den*r0| <= 0.0858 -> 3 iters ~3e-9
        float den = 1.0f + m;
        float r = fmaf(-0.5f, den, 1.45710678f);
        r = r * fmaf(-den, r, 2.0f);
        r = r * fmaf(-den, r, 2.0f);
        r = r * fmaf(-den, r, 2.0f);
        float w = (1.0f - m) * r;
        float xs = copysignf(w, v);
        acc = fmaf(w, w, acc);
        // 3-way bf16 split
        __nv_bfloat16 h = __float2bfloat16_rn(xs);
        float r1 = xs - __bfloat162float(h);
        __nv_bfloat16 md = __float2bfloat16_rn(r1);
        float r2 = r1 - __bfloat162float(md);
        __nv_bfloat16 l = __float2bfloat16_rn(r2);
        s_hm[p * 513 + c] = (uint32_t)__bfloat16_as_ushort(h)
                          | ((uint32_t)__bfloat16_as_ushort(md) << 16);
        s_lo[p * 514 + c] = __bfloat16_as_ushort(l);
    }
    s_red[tid] = acc;
    __syncthreads();

    if (tid < 32) {
        float t = 0.0f;
#pragma unroll
        for (int g = 0; g < 16; g++) t += s_red[g * 32 + tid];
        g_x2[b * 1024 + p0 + tid] = t + 512.0f;
    }

    int nb = b * 1024 + p0;
#pragma unroll 4
    for (int t = tid; t < 32 * 256; t += 512) {
        int r  = t >> 8;
        int cw = t & 255;
        uint32_t hm0 = s_hm[r * 513 + 2 * cw];
        uint32_t hm1 = s_hm[r * 513 + 2 * cw + 1];
        uint32_t hi_pair  = (hm0 & 0xffffu) | (hm1 << 16);
        uint32_t mid_pair = (hm0 >> 16) | (hm1 & 0xffff0000u);
        uint32_t lo_pair  = (uint32_t)s_lo[r * 514 + 2 * cw]
                          | ((uint32_t)s_lo[r * 514 + 2 * cw + 1] << 16);
        size_t gi = (((size_t)(cw >> 4)) * NN + nb + r) * 16 + (cw & 15);
        g_hi[gi]  = hi_pair;
        g_mid[gi] = mid_pair;
        g_lo[gi]  = lo_pair;
    }
}

// ---------------------------------------------------------------------------
// GEMM + fused argmin. grid = 256 M-tiles x 4 N-chunks (nc in low bits).
// 512 threads = 16 warps (4M x 4N), warp tile 32x64.
// ---------------------------------------------------------------------------
__global__ void __launch_bounds__(512, 1) gemm_hmma_kernel() {
    extern __shared__ char sm[];
    uint32_t smb = smem_u32(sm);

    int tid = threadIdx.x;
    int lane = tid & 31;
    int wid = tid >> 5;
    int wy = wid & 3;
    int wx = wid >> 2;          // 0..3
    int bid = blockIdx.x;
    int mt = bid >> 2;
    int nc = bid & 3;
    int rowbase = mt * M_TILE;
    int colchunk = nc * N_TILE;

    uint32_t tbaseA = (uint32_t)((wy * 32 + ((lane >> 3) & 1) * 8 + (lane & 7)) * ROW_STRIDE
                                 + (lane >> 4) * 16);
    uint32_t tbaseB = (uint32_t)(((lane >> 4) * 8 + (lane & 7)) * ROW_STRIDE
                                 + ((lane >> 3) & 1) * 16);

    const char* gA[3] = { (const char*)g_hi, (const char*)g_mid, (const char*)g_lo };

    float x2v[4];
#pragma unroll
    for (int s = 0; s < 4; s++)
        x2v[s] = g_x2[rowbase + wy * 32 + (lane >> 2) + ((s & 1) ? 8 : 0) + (s >> 1) * 16];

    float bD[4] = {INFINITY, INFINITY, INFINITY, INFINITY};
    int   bI[4] = {0, 0, 0, 0};

    float acc[2][8][4];
#pragma unroll
    for (int m = 0; m < 2; m++)
#pragma unroll
        for (int nf = 0; nf < 8; nf++)
#pragma unroll
            for (int j = 0; j < 4; j++) acc[m][nf][j] = 0.0f;

#define ISSUE_SLAB(slab, stage)                                               \
    {                                                                         \
        uint32_t dstbase = smb + (stage) * STAGE_BYTES;                       \
        _Pragma("unroll")                                                     \
        for (int i = 0; i < 5; i++) {                                         \
            int id = tid + i * 512;                                           \
            if (id < 1536) {                                                  \
                int part = id >> 9;                                           \
                int r = (id >> 2) & 127;                                      \
                int c = id & 3;                                               \
                uint32_t dst = dstbase + part * A_PHASE_BYTES                 \
                             + r * ROW_STRIDE + c * 16;                       \
                const char* src = gA[part]                                    \
                    + ((size_t)(slab) * NN + rowbase + r) * 64 + c * 16;      \
                CP_ASYNC16(dst, src);                                         \
            } else {                                                          \
                int id2 = id - 1536;                                          \
                int r = id2 >> 2;                                             \
                int c = id2 & 3;                                              \
                uint32_t dst = dstbase + 3 * A_PHASE_BYTES                    \
                             + r * ROW_STRIDE + c * 16;                       \
                const char* src = (const char*)g_cbb                          \
                    + ((size_t)(slab) * KK + colchunk + r) * 64 + c * 16;     \
                CP_ASYNC16(dst, src);                                         \
            }                                                                 \
        }                                                                     \
        CP_COMMIT();                                                          \
    }

    ISSUE_SLAB(0, 0);

    for (int s = 0; s < K_SLABS; s++) {
        if (s + 1 < K_SLABS) { ISSUE_SLAB(s + 1, (s + 1) & 1); CP_WAIT1(); }
        else                 { CP_WAIT0(); }
        __syncthreads();

        uint32_t sA = smb + (s & 1) * STAGE_BYTES;
        uint32_t sB = sA + 3 * A_PHASE_BYTES;
#pragma unroll
        for (int kk = 0; kk < 2; kk++) {
            uint32_t b[8][2];
#pragma unroll
            for (int q = 0; q < 4; q++) {
                uint32_t addr = sB + (uint32_t)((wx * 64 + q * 16) * ROW_STRIDE)
                              + tbaseB + kk * 32;
                LDSM4(b[2 * q][0], b[2 * q][1], b[2 * q + 1][0], b[2 * q + 1][1], addr);
            }
#pragma unroll
            for (int p = 0; p < 3; p++) {
                uint32_t a0[4], a1[4];
                uint32_t aaddr = sA + p * A_PHASE_BYTES + tbaseA + kk * 32;
                LDSM4(a0[0], a0[1], a0[2], a0[3], aaddr);
                LDSM4(a1[0], a1[1], a1[2], a1[3], aaddr + 16 * ROW_STRIDE);
#pragma unroll
                for (int nf = 0; nf < 8; nf++) {
                    MMA16816(acc[0][nf], a0, b[nf][0], b[nf][1]);
                    MMA16816(acc[1][nf], a1, b[nf][0], b[nf][1]);
                }
            }
        }
        __syncthreads();
    }
#undef ISSUE_SLAB

    // fused argmin over this chunk's 256 columns (ascending index)
    int colbase = colchunk + wx * 64 + (lane & 3) * 2;
#pragma unroll
    for (int nf = 0; nf < 8; nf++) {
        int cidx = colbase + nf * 8;
#pragma unroll
        for (int m = 0; m < 2; m++) {
            float d0 = fmaf(-2.0f, acc[m][nf][0], x2v[m * 2]);
            float d1 = fmaf(-2.0f, acc[m][nf][1], x2v[m * 2]);
            float d2 = fmaf(-2.0f, acc[m][nf][2], x2v[m * 2 + 1]);
            float d3 = fmaf(-2.0f, acc[m][nf][3], x2v[m * 2 + 1]);
            if (d0 < bD[m * 2])     { bD[m * 2] = d0;     bI[m * 2] = cidx; }
            if (d1 < bD[m * 2])     { bD[m * 2] = d1;     bI[m * 2] = cidx + 1; }
            if (d2 < bD[m * 2 + 1]) { bD[m * 2 + 1] = d2; bI[m * 2 + 1] = cidx; }
            if (d3 < bD[m * 2 + 1]) { bD[m * 2 + 1] = d3; bI[m * 2 + 1] = cidx + 1; }
        }
    }

#pragma unroll
    for (int off = 1; off <= 2; off <<= 1) {
#pragma unroll
        for (int s = 0; s < 4; s++) {
            float od = __shfl_xor_sync(0xffffffffu, bD[s], off);
            int   oi = __shfl_xor_sync(0xffffffffu, bI[s], off);
            if (od < bD[s] || (od == bD[s] && oi < bI[s])) { bD[s] = od; bI[s] = oi; }
        }
    }

    if ((lane & 3) == 0) {
#pragma unroll
        for (int s = 0; s < 4; s++) {
            int row = rowbase + wy * 32 + (lane >> 2) + ((s & 1) ? 8 : 0) + (s >> 1) * 16;
            uint32_t u = __float_as_uint(bD[s]);
            u = (u & 0x80000000u) ? ~u : (u | 0x80000000u);
            unsigned long long key = ((unsigned long long)u << 32) | (unsigned)bI[s];
            atomicMin(&g_best[row], key);
        }
    }
}

// ---------------------------------------------------------------------------
__global__ void gather_kernel(const float* __restrict__ cb, float* __restrict__ out) {
    int t = blockIdx.x * blockDim.x + threadIdx.x;
    int n  = t & (NN - 1);
    int cg = t >> 15;
    int idx = (int)(unsigned)(g_best[n] & 0xffffffffu);
    float4 v = ((const float4*)cb)[idx * 128 + cg];
    int b = n >> 10, p = n & 1023;
    int c = cg << 2;
    float* o = out + (((size_t)(b * 512 + c)) << 10) + p;
    o[0]    = v.x;
    o[1024] = v.y;
    o[2048] = v.z;
    o[3072] = v.w;
}

__global__ void hist_kernel() {
    __shared__ int h[KK];
    int tid = threadIdx.x;
    for (int i = tid; i < KK; i += 256) h[i] = 0;
    __syncthreads();
    int base = blockIdx.x * 1024;
    for (int i = tid; i < 1024; i += 256)
        atomicAdd(&h[(int)(unsigned)(g_best[base + i] & 0xffffffffu)], 1);
    __syncthreads();
    for (int i = tid; i < KK; i += 256) if (h[i]) atomicAdd(&g_cnt[i], h[i]);
}

__global__ void entropy_kernel(float* __restrict__ out_scalars) {
    __shared__ float s[256];
    int tid = threadIdx.x;
    float acc = 0.0f;
    for (int k = tid; k < KK; k += 256) {
        int c = g_cnt[k];
        if (c > 0) {
            float p = (float)c / 32768.0f;
            acc += p * logf(p);
        }
    }
    s[tid] = acc;
    __syncthreads();
    for (int o = 128; o > 0; o >>= 1) {
        if (tid < o) s[tid] += s[tid + o];
        __syncthreads();
    }
    if (tid == 0) {
        float entropy = -s[0];
        float perp = expf(entropy);
        float pl = 1.0f / perp;
        out_scalars[0] = pl;
        out_scalars[1] = 0.25f * pl;
    }
}

// ---------------------------------------------------------------------------
extern "C" void kernel_launch(void* const* d_in, const int* in_sizes, int n_in,
                              void* d_out, int out_size) {
    const float* x  = (const float*)d_in[0];
    const float* cb = (const float*)d_in[1];
    float* out = (float*)d_out;

    cudaFuncSetAttribute(prep_kernel, cudaFuncAttributeMaxDynamicSharedMemorySize, PREP_SMEM);
    cudaFuncSetAttribute(gemm_hmma_kernel, cudaFuncAttributeMaxDynamicSharedMemorySize, GEMM_SMEM);

    init_best_kernel<<<NN / 256, 256>>>();
    zero_counts_kernel<<<4, 256>>>();
    cb_bf16_kernel<<<1024, 256>>>(cb);
    prep_kernel<<<1024, 512, PREP_SMEM>>>(x);
    gemm_hmma_kernel<<<(NN / M_TILE) * (KK / N_TILE), 512, GEMM_SMEM>>>();
    gather_kernel<<<(NN * 128) / 256, 256>>>(cb, out);
    hist_kernel<<<NN / 1024, 256>>>();
    if (out_size >= QE + 2) {
        entropy_kernel<<<1, 256>>>(out + QE);
    }
}